// round 2
// baseline (speedup 1.0000x reference)
#include <cuda_runtime.h>
#include <math.h>

// Problem shape (fixed for this dataset entry)
#define BATCH 1024
#define SEQL  512
#define NTAG  64
#define WARPS_PER_CTA 8
#define CTA_THREADS (WARPS_PER_CTA * 32)

// CRF forward NLL:
//   alpha_0 = emit_0
//   alpha_t[j] = mask_t ? ( emit_t[j] + logsumexp_i( alpha_{t-1}[i] + trans[i][j] ) ) : alpha_{t-1}[j]
//   logZ = logsumexp_j alpha_{L-1}[j]
//   gold = sum_t emit_t[tag_t]*mask_t + sum_{t>=1} trans[tag_{t-1}][tag_t]*mask_t
//   out[b] = logZ - gold
//
// Transform: E[i][j] = exp(trans[i][j] - cmax[j]),  cmax[j] = max_i trans[i][j]
//   alpha_t[j] = emit_t[j] + m + cmax[j] + log( sum_i exp(alpha_{t-1}[i]-m) * E[i][j] )
// -> inner step is a 64x64 FFMA matvec instead of 4096 exps.
//
// Tags dtype is ambiguous (reference asks for int64; JAX may downcast to
// int32). Detect at runtime: int64 little-endian with values in [0,64) has
// every odd 32-bit word == 0; int32 random tags make that astronomically
// unlikely over 32 odd words. Deterministic, once per CTA.

__global__ __launch_bounds__(CTA_THREADS, 1)
void crf_fwd_kernel(const float* __restrict__ logits,
                    const int*   __restrict__ tags32,   // raw tag words (int32 view)
                    const int*   __restrict__ mask,
                    const float* __restrict__ trans,
                    float* __restrict__ out)
{
    __shared__ float2 E2[NTAG][32];          // E2[i][l] = { E[i][2l], E[i][2l+1] }  (16 KB)
    __shared__ float  trans_s[NTAG * NTAG];  // raw transitions (16 KB)
    __shared__ float2 cmax2[32];
    __shared__ float  pbuf[WARPS_PER_CTA][2][NTAG];  // per-warp p, double-buffered (4 KB)
    __shared__ int    tags_is64_s;

    const int tid  = threadIdx.x;
    const int warp = tid >> 5;
    const int lane = tid & 31;

    // ---- per-CTA init: load trans, detect tag dtype ----
    for (int k = tid; k < NTAG * NTAG; k += CTA_THREADS)
        trans_s[k] = trans[k];
    if (tid == 0) {
        int odd_or = 0;
        #pragma unroll
        for (int w = 1; w < 64; w += 2)
            odd_or |= tags32[w];
        tags_is64_s = (odd_or == 0) ? 1 : 0;
    }
    __syncthreads();

    if (tid < NTAG) {
        float m = -3.402823466e38f;
        #pragma unroll
        for (int i = 0; i < NTAG; i++)
            m = fmaxf(m, trans_s[i * NTAG + tid]);
        reinterpret_cast<float*>(cmax2)[tid] = m;
    }
    __syncthreads();

    for (int k = tid; k < NTAG * NTAG; k += CTA_THREADS) {
        const int j = k & (NTAG - 1);
        reinterpret_cast<float*>(E2)[k] =
            __expf(trans_s[k] - reinterpret_cast<const float*>(cmax2)[j]);
    }
    __syncthreads();

    const bool is64 = (tags_is64_s != 0);

    // ---- one warp per batch chain ----
    const int b = blockIdx.x * WARPS_PER_CTA + warp;

    const float* emit_base = logits + (size_t)b * SEQL * NTAG;
    const int*   mask_base = mask   + (size_t)b * SEQL;
    // tag word index for element t of batch b, in int32 units:
    //   is64: 2*(b*SEQL + t)   (low word)   else: b*SEQL + t
    const size_t tbase = (size_t)b * SEQL;

    auto load_tag = [&](int t) -> int {
        return is64 ? tags32[2 * (tbase + t)] : tags32[tbase + t];
    };

    const int j0 = 2 * lane;
    const float2 cm = cmax2[lane];

    // t = 0: alpha init + gold emission
    float2 a = *reinterpret_cast<const float2*>(emit_base + j0);
    int   tg_prev = load_tag(0);
    float mk0     = (float)mask_base[0];
    float gold = 0.0f;
    if (tg_prev == j0)          gold = a.x * mk0;
    else if (tg_prev == j0 + 1) gold = a.y * mk0;

    // prefetch t = 1
    float2 em = *reinterpret_cast<const float2*>(emit_base + NTAG + j0);
    int    tg = load_tag(1);
    float  mk = (float)mask_base[1];

    int buf = 0;
    for (int t = 1; t < SEQL; t++) {
        // prefetch t+1 (hide DRAM latency under this step's compute)
        float2 em_n = make_float2(0.f, 0.f);
        int    tg_n = 0;
        float  mk_n = 0.f;
        if (t + 1 < SEQL) {
            em_n = *reinterpret_cast<const float2*>(emit_base + (size_t)(t + 1) * NTAG + j0);
            tg_n = load_tag(t + 1);
            mk_n = (float)mask_base[t + 1];
        }

        // m = max_i alpha[i]  (warp reduction over 64 values, 2 per lane)
        float m = fmaxf(a.x, a.y);
        #pragma unroll
        for (int o = 16; o > 0; o >>= 1)
            m = fmaxf(m, __shfl_xor_sync(0xffffffffu, m, o));

        // p = exp(alpha - m), publish to shared
        float2 p;
        p.x = __expf(a.x - m);
        p.y = __expf(a.y - m);
        *reinterpret_cast<float2*>(&pbuf[warp][buf][j0]) = p;
        __syncwarp();

        // matvec: acc[j] = sum_i p[i] * E[i][j]   (4 independent FMA chains)
        const float* pb = pbuf[warp][buf];
        float acc0 = 0.f, acc1 = 0.f, acc2 = 0.f, acc3 = 0.f;
        #pragma unroll
        for (int i = 0; i < NTAG; i += 2) {
            const float2 pp = *reinterpret_cast<const float2*>(pb + i); // broadcast
            const float2 e0 = E2[i][lane];
            const float2 e1 = E2[i + 1][lane];
            acc0 = fmaf(pp.x, e0.x, acc0);
            acc1 = fmaf(pp.x, e0.y, acc1);
            acc2 = fmaf(pp.y, e1.x, acc2);
            acc3 = fmaf(pp.y, e1.y, acc3);
        }
        const float s0 = acc0 + acc2;
        const float s1 = acc1 + acc3;

        const float na0 = m + cm.x + __logf(s0) + em.x;
        const float na1 = m + cm.y + __logf(s1) + em.y;
        if (mk > 0.f) { a.x = na0; a.y = na1; }

        // gold score contributions for step t
        if (tg == j0)          gold += em.x * mk;
        else if (tg == j0 + 1) gold += em.y * mk;
        if (lane == 0)
            gold += trans_s[tg_prev * NTAG + tg] * mk;
        tg_prev = tg;

        em = em_n; tg = tg_n; mk = mk_n;
        buf ^= 1;
    }

    // logZ = logsumexp(alpha)
    float m = fmaxf(a.x, a.y);
    #pragma unroll
    for (int o = 16; o > 0; o >>= 1)
        m = fmaxf(m, __shfl_xor_sync(0xffffffffu, m, o));
    float s = __expf(a.x - m) + __expf(a.y - m);
    #pragma unroll
    for (int o = 16; o > 0; o >>= 1)
        s += __shfl_xor_sync(0xffffffffu, s, o);
    const float logZ = m + __logf(s);

    // reduce gold across warp
    #pragma unroll
    for (int o = 16; o > 0; o >>= 1)
        gold += __shfl_xor_sync(0xffffffffu, gold, o);

    if (lane == 0)
        out[b] = logZ - gold;
}

extern "C" void kernel_launch(void* const* d_in, const int* in_sizes, int n_in,
                              void* d_out, int out_size)
{
    const float* logits = (const float*)d_in[0];
    const int*   tags32 = (const int*)d_in[1];   // dtype detected in-kernel
    const int*   mask   = (const int*)d_in[2];
    const float* trans  = (const float*)d_in[3];
    float*       out    = (float*)d_out;

    const int grid = BATCH / WARPS_PER_CTA; // 128 CTAs, 8 warps (batches) each
    crf_fwd_kernel<<<grid, CTA_THREADS>>>(logits, tags32, mask, trans, out);
}

// round 5
// speedup vs baseline: 1.3517x; 1.3517x over previous
#include <cuda_runtime.h>
#include <math.h>

// Problem shape (fixed for this dataset entry)
#define BATCH 1024
#define SEQL  512
#define NTAG  64
#define WARPS_PER_CTA 8
#define CTA_THREADS (WARPS_PER_CTA * 32)

// CRF forward NLL (see round-1 derivation):
//   E[i][j] = exp(trans[i][j] - cmax[j])
//   alpha_t[j] = emit_t[j] + m + cmax[j] + log( sum_i exp(alpha_{t-1}[i]-m) * E[i][j] )
//
// Round-3 changes:
//  * E lives in REGISTERS (128 floats / lane, packed as 64x u64 f32x2 operands)
//    -> kills the smem-crossbar bottleneck (was 77% L1 throughput).
//  * inner matvec uses packed fma.rn.f32x2 (Blackwell FFMA2): one instruction
//    does both of a lane's columns for one i. p published to shared
//    pre-duplicated {p,p} so a broadcast LDS.128 yields two ready operands.

__device__ __forceinline__ unsigned long long pack_f32x2(float lo, float hi) {
    return ((unsigned long long)__float_as_uint(hi) << 32) | __float_as_uint(lo);
}
__device__ __forceinline__ float lo_f32(unsigned long long v) {
    return __uint_as_float((unsigned)(v & 0xffffffffull));
}
__device__ __forceinline__ float hi_f32(unsigned long long v) {
    return __uint_as_float((unsigned)(v >> 32));
}
__device__ __forceinline__ unsigned long long fma_f32x2(unsigned long long a,
                                                        unsigned long long b,
                                                        unsigned long long c) {
    unsigned long long d;
    asm("fma.rn.f32x2 %0, %1, %2, %3;" : "=l"(d) : "l"(a), "l"(b), "l"(c));
    return d;
}
__device__ __forceinline__ unsigned long long add_f32x2(unsigned long long a,
                                                        unsigned long long b) {
    unsigned long long d;
    asm("add.rn.f32x2 %0, %1, %2;" : "=l"(d) : "l"(a), "l"(b));
    return d;
}

__global__ __launch_bounds__(CTA_THREADS, 1)
void crf_fwd_kernel(const float* __restrict__ logits,
                    const int*   __restrict__ tags32,   // raw tag words (int32 view)
                    const int*   __restrict__ mask,
                    const float* __restrict__ trans,
                    float* __restrict__ out)
{
    __shared__ float  trans_s[NTAG * NTAG];   // raw transitions (16 KB) — gold lookups
    __shared__ float  cmax_s[NTAG];
    // p double-buffer, entries pre-duplicated: pb[w][buf][i] = {p_i, p_i}
    __shared__ __align__(16) float2 pb[WARPS_PER_CTA][2][NTAG];   // 8 KB
    __shared__ int tags_is64_s;

    const int tid  = threadIdx.x;
    const int warp = tid >> 5;
    const int lane = tid & 31;

    // ---- per-CTA init ----
    for (int k = tid; k < NTAG * NTAG; k += CTA_THREADS)
        trans_s[k] = trans[k];
    if (tid == 0) {
        int odd_or = 0;
        #pragma unroll
        for (int w = 1; w < 64; w += 2)
            odd_or |= tags32[w];
        tags_is64_s = (odd_or == 0) ? 1 : 0;   // int64 tags: odd words all zero
    }
    __syncthreads();

    if (tid < NTAG) {
        float m = -3.402823466e38f;
        #pragma unroll
        for (int i = 0; i < NTAG; i++)
            m = fmaxf(m, trans_s[i * NTAG + tid]);
        cmax_s[tid] = m;
    }
    __syncthreads();

    const bool is64 = (tags_is64_s != 0);
    const int  j0   = 2 * lane;
    const float2 cm = make_float2(cmax_s[j0], cmax_s[j0 + 1]);

    // ---- E into registers: E_r[i] = { exp(trans[i][j0]-cm.x), exp(trans[i][j0+1]-cm.y) }
    unsigned long long E_r[NTAG];
    #pragma unroll
    for (int i = 0; i < NTAG; i++) {
        const float ex = __expf(trans_s[i * NTAG + j0]     - cm.x);
        const float ey = __expf(trans_s[i * NTAG + j0 + 1] - cm.y);
        E_r[i] = pack_f32x2(ex, ey);
    }

    // ---- one warp per batch chain ----
    const int b = blockIdx.x * WARPS_PER_CTA + warp;

    const float* emit_base = logits + (size_t)b * SEQL * NTAG;
    const int*   mask_base = mask   + (size_t)b * SEQL;
    const size_t tbase     = (size_t)b * SEQL;

    auto load_tag = [&](int t) -> int {
        return is64 ? tags32[2 * (tbase + t)] : tags32[tbase + t];
    };

    // t = 0: alpha init + gold emission
    float2 a = *reinterpret_cast<const float2*>(emit_base + j0);
    int   tg_prev = load_tag(0);
    float mk0     = (float)mask_base[0];
    float gold = 0.0f;
    if (tg_prev == j0)          gold = a.x * mk0;
    else if (tg_prev == j0 + 1) gold = a.y * mk0;

    // prefetch t = 1
    float2 em = *reinterpret_cast<const float2*>(emit_base + NTAG + j0);
    int    tg = load_tag(1);
    float  mk = (float)mask_base[1];

    int buf = 0;
    for (int t = 1; t < SEQL; t++) {
        // prefetch t+1 (hide DRAM latency under this step's compute)
        float2 em_n = make_float2(0.f, 0.f);
        int    tg_n = 0;
        float  mk_n = 0.f;
        if (t + 1 < SEQL) {
            em_n = *reinterpret_cast<const float2*>(emit_base + (size_t)(t + 1) * NTAG + j0);
            tg_n = load_tag(t + 1);
            mk_n = (float)mask_base[t + 1];
        }

        // m = max_i alpha[i]
        float m = fmaxf(a.x, a.y);
        #pragma unroll
        for (int o = 16; o > 0; o >>= 1)
            m = fmaxf(m, __shfl_xor_sync(0xffffffffu, m, o));

        // p = exp(alpha - m), publish duplicated {p,p} pairs (one STS.128)
        const float px = __expf(a.x - m);
        const float py = __expf(a.y - m);
        *reinterpret_cast<float4*>(&pb[warp][buf][j0]) =
            make_float4(px, px, py, py);
        __syncwarp();

        // matvec: acc[j0], acc[j0+1] += p[i] * E[i][j]  (packed f32x2, 4 chains)
        const float4* pbp = reinterpret_cast<const float4*>(&pb[warp][buf][0]);
        unsigned long long acc0 = 0ull, acc1 = 0ull, acc2 = 0ull, acc3 = 0ull;
        #pragma unroll
        for (int k = 0; k < NTAG / 4; k++) {            // 16 iterations, i = 4k..4k+3
            const float4 q0 = pbp[2 * k];               // {p_i,p_i,p_{i+1},p_{i+1}}
            const float4 q1 = pbp[2 * k + 1];
            const unsigned long long pA = pack_f32x2(q0.x, q0.y);  // becomes MOV64 of loaded pair
            const unsigned long long pB = pack_f32x2(q0.z, q0.w);
            const unsigned long long pC = pack_f32x2(q1.x, q1.y);
            const unsigned long long pD = pack_f32x2(q1.z, q1.w);
            acc0 = fma_f32x2(pA, E_r[4 * k],     acc0);
            acc1 = fma_f32x2(pB, E_r[4 * k + 1], acc1);
            acc2 = fma_f32x2(pC, E_r[4 * k + 2], acc2);
            acc3 = fma_f32x2(pD, E_r[4 * k + 3], acc3);
        }
        const unsigned long long s01 = add_f32x2(acc0, acc1);
        const unsigned long long s23 = add_f32x2(acc2, acc3);
        const unsigned long long sp  = add_f32x2(s01, s23);
        const float s0 = lo_f32(sp);
        const float s1 = hi_f32(sp);

        const float na0 = m + cm.x + __logf(s0) + em.x;
        const float na1 = m + cm.y + __logf(s1) + em.y;
        if (mk > 0.f) { a.x = na0; a.y = na1; }

        // gold score contributions for step t
        if (tg == j0)          gold += em.x * mk;
        else if (tg == j0 + 1) gold += em.y * mk;
        if (lane == 0)
            gold += trans_s[tg_prev * NTAG + tg] * mk;
        tg_prev = tg;

        em = em_n; tg = tg_n; mk = mk_n;
        buf ^= 1;
    }

    // logZ = logsumexp(alpha)
    float m = fmaxf(a.x, a.y);
    #pragma unroll
    for (int o = 16; o > 0; o >>= 1)
        m = fmaxf(m, __shfl_xor_sync(0xffffffffu, m, o));
    float s = __expf(a.x - m) + __expf(a.y - m);
    #pragma unroll
    for (int o = 16; o > 0; o >>= 1)
        s += __shfl_xor_sync(0xffffffffu, s, o);
    const float logZ = m + __logf(s);

    // reduce gold across warp
    #pragma unroll
    for (int o = 16; o > 0; o >>= 1)
        gold += __shfl_xor_sync(0xffffffffu, gold, o);

    if (lane == 0)
        out[b] = logZ - gold;
}

extern "C" void kernel_launch(void* const* d_in, const int* in_sizes, int n_in,
                              void* d_out, int out_size)
{
    const float* logits = (const float*)d_in[0];
    const int*   tags32 = (const int*)d_in[1];   // dtype detected in-kernel
    const int*   mask   = (const int*)d_in[2];
    const float* trans  = (const float*)d_in[3];
    float*       out    = (float*)d_out;

    const int grid = BATCH / WARPS_PER_CTA; // 128 CTAs, 8 warps (batches) each
    crf_fwd_kernel<<<grid, CTA_THREADS>>>(logits, tags32, mask, trans, out);
}